// round 4
// baseline (speedup 1.0000x reference)
#include <cuda_runtime.h>

#define NB    32
#define NC    3
#define NT    128000
#define NT4   (NT/4)        // 32000 float4 per (b,c)
#define TSUB  1000
#define TF    8000
#define NBLK  16            // blocks per batch for the moment pass
#define TPB   256
#define NQ    21            // 3 sum_x + 3 sum_y + 9 sum_xy + 3 sum_xx + 3 sum_yy
#define EPSF  1e-8f
#define FULLM 0xffffffffu
#define GRID  (NB * NBLK + NB)   // 544 blocks

__device__ float g_part[NB * NBLK * NQ];
__device__ float g_D[NB * 9];
__device__ int   g_count;        // zero-init at load; self-resets each launch

__device__ __forceinline__ float warp_sum(float v) {
#pragma unroll
    for (int o = 16; o > 0; o >>= 1) v += __shfl_down_sync(FULLM, v, o);
    return v;
}

__global__ void __launch_bounds__(TPB)
fused_kernel(const float* __restrict__ sep, const float* __restrict__ src,
             const float* __restrict__ diar, const float* __restrict__ labels,
             const float* __restrict__ exist, const int* __restrict__ nspk,
             float* __restrict__ out)
{
    const int blk  = blockIdx.x;
    const int tid  = threadIdx.x;
    const int lane = tid & 31;
    const int warp = tid >> 5;
    __shared__ float sm[TPB / 32][NQ];
    __shared__ bool  sm_last;

    if (blk < NB * NBLK) {
        // ---- streaming moment accumulation over T ----
        const int b  = blk / NBLK;
        const int bb = blk % NBLK;
        const float4* x0 = (const float4*)(sep + (size_t)(b * 3 + 0) * NT);
        const float4* x1 = (const float4*)(sep + (size_t)(b * 3 + 1) * NT);
        const float4* x2 = (const float4*)(sep + (size_t)(b * 3 + 2) * NT);
        const float4* y0 = (const float4*)(src + (size_t)(b * 3 + 0) * NT);
        const float4* y1 = (const float4*)(src + (size_t)(b * 3 + 1) * NT);
        const float4* y2 = (const float4*)(src + (size_t)(b * 3 + 2) * NT);
        const int chunk = NT4 / NBLK;      // 2000
        const int lo = bb * chunk;
        const int hi = lo + chunk;

        float acc[NQ];
#pragma unroll
        for (int q = 0; q < NQ; q++) acc[q] = 0.f;

        for (int i = lo + tid; i < hi; i += TPB) {
            float4 a0 = x0[i], a1 = x1[i], a2 = x2[i];
            float4 c0 = y0[i], c1 = y1[i], c2 = y2[i];
            const float* pa0 = (const float*)&a0;
            const float* pa1 = (const float*)&a1;
            const float* pa2 = (const float*)&a2;
            const float* pc0 = (const float*)&c0;
            const float* pc1 = (const float*)&c1;
            const float* pc2 = (const float*)&c2;
#pragma unroll
            for (int k = 0; k < 4; k++) {
                float xa = pa0[k], xb = pa1[k], xc = pa2[k];
                float ya = pc0[k], yb = pc1[k], yc = pc2[k];
                acc[0]  += xa;      acc[1]  += xb;      acc[2]  += xc;
                acc[3]  += ya;      acc[4]  += yb;      acc[5]  += yc;
                acc[6]  += xa * ya; acc[7]  += xa * yb; acc[8]  += xa * yc;
                acc[9]  += xb * ya; acc[10] += xb * yb; acc[11] += xb * yc;
                acc[12] += xc * ya; acc[13] += xc * yb; acc[14] += xc * yc;
                acc[15] += xa * xa; acc[16] += xb * xb; acc[17] += xc * xc;
                acc[18] += ya * ya; acc[19] += yb * yb; acc[20] += yc * yc;
            }
        }
#pragma unroll
        for (int q = 0; q < NQ; q++) {
            float v = warp_sum(acc[q]);
            if (lane == 0) sm[warp][q] = v;
        }
        __syncthreads();
        if (warp == 0 && lane < NQ) {
            float s = 0.f;
#pragma unroll
            for (int w = 0; w < TPB / 32; w++) s += sm[w][lane];
            g_part[blk * NQ + lane] = s;
        }
    } else {
        // ---- diarization BCE matrix for one batch ----
        const int b = blk - NB * NBLK;
        const float* dp = diar   + (size_t)b * TSUB * 3;
        const float* lb = labels + (size_t)b * TF * 3;
        float acc[9];
#pragma unroll
        for (int q = 0; q < 9; q++) acc[q] = 0.f;

        for (int t = tid; t < TSUB; t += TPB) {
            float p0 = dp[t * 3 + 0], p1 = dp[t * 3 + 1], p2 = dp[t * 3 + 2];
            // idx = floor(t * (8000/1000)) = 8t
            float l0 = lb[t * 24 + 0], l1 = lb[t * 24 + 1], l2 = lb[t * 24 + 2];
            float lp0 = fmaxf(__logf(p0), -100.f);
            float lp1 = fmaxf(__logf(p1), -100.f);
            float lp2 = fmaxf(__logf(p2), -100.f);
            float lq0 = fmaxf(__logf(1.f - p0), -100.f);
            float lq1 = fmaxf(__logf(1.f - p1), -100.f);
            float lq2 = fmaxf(__logf(1.f - p2), -100.f);
            float m0 = 1.f - l0, m1 = 1.f - l1, m2 = 1.f - l2;
            acc[0] += lp0 * l0 + lq0 * m0;
            acc[1] += lp0 * l1 + lq0 * m1;
            acc[2] += lp0 * l2 + lq0 * m2;
            acc[3] += lp1 * l0 + lq1 * m0;
            acc[4] += lp1 * l1 + lq1 * m1;
            acc[5] += lp1 * l2 + lq1 * m2;
            acc[6] += lp2 * l0 + lq2 * m0;
            acc[7] += lp2 * l1 + lq2 * m1;
            acc[8] += lp2 * l2 + lq2 * m2;
        }
#pragma unroll
        for (int q = 0; q < 9; q++) {
            float v = warp_sum(acc[q]);
            if (lane == 0) sm[warp][q] = v;
        }
        __syncthreads();
        if (warp == 0 && lane < 9) {
            float s = 0.f;
#pragma unroll
            for (int w = 0; w < TPB / 32; w++) s += sm[w][lane];
            g_D[b * 9 + lane] = s;
        }
    }

    // ---- last-block-done gate ----
    __syncthreads();
    if (tid == 0) {
        __threadfence();
        int prev = atomicAdd(&g_count, 1);
        sm_last = (prev == GRID - 1);
    }
    __syncthreads();
    if (!sm_last) return;
    __threadfence();   // acquire: make all other blocks' partials visible

    // ================= finalize (one block, 8 warps, 4 batches/warp) ========
    __shared__ float sm_s[NB], sm_d[NB], sm_e[NB];

    // perms: {012,021,102,120,201,210}, 2 bits/entry, 6 bits/perm
    const unsigned long long PP =
        0x24ULL | (0x18ULL << 6) | (0x21ULL << 12) |
        (0x09ULL << 18) | (0x12ULL << 24) | (0x06ULL << 30);

#pragma unroll
    for (int it = 0; it < NB / (TPB / 32); it++) {
        const int b = warp + it * (TPB / 32);

        // transposed partial reduction: lane q sums its statistic
        const int q = min(lane, NQ - 1);
        float sq = 0.f;
        {
            const float* base = g_part + (size_t)(b * NBLK) * NQ + q;
#pragma unroll
            for (int k = 0; k < NBLK; k++) sq += base[k * NQ];
        }
        const int l = min(lane, 8);
        const float dval = g_D[b * 9 + l];
        const float pex  = exist[b * 4 + (lane & 3)];
        const int ns_raw = nspk[b];
        const int ns = min(max(ns_raw, 1), 3);

        // lane l computes S[i][j], D[i][j] for l = 3*i + j
        const int i3 = l / 3, j3 = l % 3;
        const float fT = (float)NT;
        float sx  = __shfl_sync(FULLM, sq, i3);
        float sy  = __shfl_sync(FULLM, sq, 3 + j3);
        float sxy = __shfl_sync(FULLM, sq, 6 + l);
        float sxx = __shfl_sync(FULLM, sq, 15 + i3);
        float syy = __shfl_sync(FULLM, sq, 18 + j3);

        float mx = sx / fT, my = sy / fT;
        float estsq = sxx - fT * mx * mx;
        float tgtsq = syy - fT * my * my;
        float dotc  = sxy - fT * mx * my;
        float al  = __fdividef(dotc, tgtsq + EPSF);
        float a2t = al * al * tgtsq;
        float sig = a2t + EPSF;
        float noi = estsq - 2.f * al * dotc + a2t + EPSF;
        float S_l = 10.f * __log10f(__fdividef(sig, noi));
        float D_l = -dval * (1.f / (float)TSUB);

        // lane p evaluates permutation p
        const int p = min(lane, 5);
        bool valid = true;
        float ss = 0.f, dd = 0.f;
#pragma unroll
        for (int slot = 0; slot < 3; slot++) {
            int pi = (int)((PP >> (p * 6 + slot * 2)) & 3ULL);
            int srci = pi * 3 + slot;
            float Sv = __shfl_sync(FULLM, S_l, srci);
            float Dv = __shfl_sync(FULLM, D_l, srci);
            if (!(pi < ns || slot >= ns)) valid = false;
            if (slot < ns) { ss += Sv; dd += Dv; }
        }
        const float inv_n = 1.f / (float)ns;
        float cand_s = valid ? -ss * inv_n : 3.4e38f;
        float cand_d = valid ?  dd * inv_n : 3.4e38f;

        // exist BCE: lanes 0..3
        float ev = 0.f;
        if (lane < 4) {
            const int nex = min(ns_raw, 3);
            float t = (lane < nex) ? 1.f : 0.f;
            ev = -(t * fmaxf(__logf(pex), -100.f) +
                   (1.f - t) * fmaxf(__logf(1.f - pex), -100.f));
        }

#pragma unroll
        for (int o = 16; o > 0; o >>= 1) {
            cand_s = fminf(cand_s, __shfl_xor_sync(FULLM, cand_s, o));
            cand_d = fminf(cand_d, __shfl_xor_sync(FULLM, cand_d, o));
            ev    += __shfl_xor_sync(FULLM, ev, o);
        }
        if (lane == 0) { sm_s[b] = cand_s; sm_d[b] = cand_d; sm_e[b] = ev; }
    }
    __syncthreads();

    if (warp == 0) {
        float rs = warp_sum(sm_s[lane]);
        float rd = warp_sum(sm_d[lane]);
        float re = warp_sum(sm_e[lane]);
        if (lane == 0) {
            float loss_sisnr = rs * (1.f / (float)NB);
            float loss_diar  = rd * (1.f / (float)NB);
            float loss_exist = re * (1.f / (float)(NB * 4));
            float total = loss_sisnr + 0.2f * loss_diar + 0.2f * loss_exist;
            out[0] = total;
            out[1] = loss_sisnr;
            out[2] = loss_diar;
            out[3] = loss_exist;
            out[4] = -loss_sisnr;   // mean_sisnr == -loss_sisnr exactly
            g_count = 0;            // reset for next (deterministic) replay
        }
    }
}

extern "C" void kernel_launch(void* const* d_in, const int* in_sizes, int n_in,
                              void* d_out, int out_size)
{
    const float* sep = nullptr;
    const float* src = nullptr;
    const float* diar = nullptr;
    const float* lab = nullptr;
    const float* ex = nullptr;
    const int*   ns = nullptr;

    for (int i = 0; i < n_in; i++) {
        switch (in_sizes[i]) {
            case NB * NC * NT:       // 12,288,000: separated first, sources second
                if (!sep) sep = (const float*)d_in[i];
                else       src = (const float*)d_in[i];
                break;
            case NB * TSUB * NC:     // 96,000
                diar = (const float*)d_in[i]; break;
            case NB * (NC + 1):      // 128
                ex = (const float*)d_in[i]; break;
            case NB * TF * NC:       // 768,000
                lab = (const float*)d_in[i]; break;
            case NB:                 // 32
                ns = (const int*)d_in[i]; break;
            default: break;
        }
    }

    fused_kernel<<<GRID, TPB>>>(sep, src, diar, lab, ex, ns, (float*)d_out);
}

// round 5
// speedup vs baseline: 1.2037x; 1.2037x over previous
#include <cuda_runtime.h>

#define NB    32
#define NC    3
#define NT    128000
#define NT4   (NT/4)        // 32000 float4 per (b,c)
#define TSUB  1000
#define TF    8000
#define NBLK  16            // blocks per batch for the moment pass
#define TPB   256
#define NQ    21            // 3 sum_x + 3 sum_y + 9 sum_xy + 3 sum_xx + 3 sum_yy
#define EPSF  1e-8f
#define FULLM 0xffffffffu

__device__ float g_part[NB * NBLK * NQ];
__device__ float g_D[NB * 9];

__device__ __forceinline__ float warp_sum(float v) {
#pragma unroll
    for (int o = 16; o > 0; o >>= 1) v += __shfl_down_sync(FULLM, v, o);
    return v;
}

__global__ void __launch_bounds__(TPB)
main_kernel(const float* __restrict__ sep, const float* __restrict__ src,
            const float* __restrict__ diar, const float* __restrict__ labels)
{
    const int blk  = blockIdx.x;
    const int tid  = threadIdx.x;
    const int lane = tid & 31;
    const int warp = tid >> 5;
    __shared__ float sm[TPB / 32][NQ];

    if (blk < NB * NBLK) {
        // ---- streaming moment accumulation over T ----
        const int b  = blk / NBLK;
        const int bb = blk % NBLK;
        const float4* x0 = (const float4*)(sep + (size_t)(b * 3 + 0) * NT);
        const float4* x1 = (const float4*)(sep + (size_t)(b * 3 + 1) * NT);
        const float4* x2 = (const float4*)(sep + (size_t)(b * 3 + 2) * NT);
        const float4* y0 = (const float4*)(src + (size_t)(b * 3 + 0) * NT);
        const float4* y1 = (const float4*)(src + (size_t)(b * 3 + 1) * NT);
        const float4* y2 = (const float4*)(src + (size_t)(b * 3 + 2) * NT);
        const int chunk = NT4 / NBLK;      // 2000
        const int lo = bb * chunk;
        const int hi = lo + chunk;

        float acc[NQ];
#pragma unroll
        for (int q = 0; q < NQ; q++) acc[q] = 0.f;

        for (int i = lo + tid; i < hi; i += TPB) {
            float4 a0 = x0[i], a1 = x1[i], a2 = x2[i];
            float4 c0 = y0[i], c1 = y1[i], c2 = y2[i];
            const float* pa0 = (const float*)&a0;
            const float* pa1 = (const float*)&a1;
            const float* pa2 = (const float*)&a2;
            const float* pc0 = (const float*)&c0;
            const float* pc1 = (const float*)&c1;
            const float* pc2 = (const float*)&c2;
#pragma unroll
            for (int k = 0; k < 4; k++) {
                float xa = pa0[k], xb = pa1[k], xc = pa2[k];
                float ya = pc0[k], yb = pc1[k], yc = pc2[k];
                acc[0]  += xa;      acc[1]  += xb;      acc[2]  += xc;
                acc[3]  += ya;      acc[4]  += yb;      acc[5]  += yc;
                acc[6]  += xa * ya; acc[7]  += xa * yb; acc[8]  += xa * yc;
                acc[9]  += xb * ya; acc[10] += xb * yb; acc[11] += xb * yc;
                acc[12] += xc * ya; acc[13] += xc * yb; acc[14] += xc * yc;
                acc[15] += xa * xa; acc[16] += xb * xb; acc[17] += xc * xc;
                acc[18] += ya * ya; acc[19] += yb * yb; acc[20] += yc * yc;
            }
        }
#pragma unroll
        for (int q = 0; q < NQ; q++) {
            float v = warp_sum(acc[q]);
            if (lane == 0) sm[warp][q] = v;
        }
        __syncthreads();
        if (warp == 0 && lane < NQ) {
            float s = 0.f;
#pragma unroll
            for (int w = 0; w < TPB / 32; w++) s += sm[w][lane];
            g_part[blk * NQ + lane] = s;
        }
    } else {
        // ---- diarization BCE matrix for one batch ----
        const int b = blk - NB * NBLK;
        const float* dp = diar   + (size_t)b * TSUB * 3;
        const float* lb = labels + (size_t)b * TF * 3;
        float acc[9];
#pragma unroll
        for (int q = 0; q < 9; q++) acc[q] = 0.f;

        for (int t = tid; t < TSUB; t += TPB) {
            float p0 = dp[t * 3 + 0], p1 = dp[t * 3 + 1], p2 = dp[t * 3 + 2];
            // idx = floor(t * (8000/1000)) = 8t
            float l0 = lb[t * 24 + 0], l1 = lb[t * 24 + 1], l2 = lb[t * 24 + 2];
            float lp0 = fmaxf(__logf(p0), -100.f);
            float lp1 = fmaxf(__logf(p1), -100.f);
            float lp2 = fmaxf(__logf(p2), -100.f);
            float lq0 = fmaxf(__logf(1.f - p0), -100.f);
            float lq1 = fmaxf(__logf(1.f - p1), -100.f);
            float lq2 = fmaxf(__logf(1.f - p2), -100.f);
            float m0 = 1.f - l0, m1 = 1.f - l1, m2 = 1.f - l2;
            acc[0] += lp0 * l0 + lq0 * m0;
            acc[1] += lp0 * l1 + lq0 * m1;
            acc[2] += lp0 * l2 + lq0 * m2;
            acc[3] += lp1 * l0 + lq1 * m0;
            acc[4] += lp1 * l1 + lq1 * m1;
            acc[5] += lp1 * l2 + lq1 * m2;
            acc[6] += lp2 * l0 + lq2 * m0;
            acc[7] += lp2 * l1 + lq2 * m1;
            acc[8] += lp2 * l2 + lq2 * m2;
        }
#pragma unroll
        for (int q = 0; q < 9; q++) {
            float v = warp_sum(acc[q]);
            if (lane == 0) sm[warp][q] = v;
        }
        __syncthreads();
        if (warp == 0 && lane < 9) {
            float s = 0.f;
#pragma unroll
            for (int w = 0; w < TPB / 32; w++) s += sm[w][lane];
            g_D[b * 9 + lane] = s;
        }
    }

    // allow the dependent finalize grid to launch as this block retires
    __syncthreads();
    cudaTriggerProgrammaticLaunchCompletion();
}

// Lane-parallel finalize: warp b handles batch b.
__global__ void __launch_bounds__(NB * 32)
finalize_kernel(const float* __restrict__ exist, const int* __restrict__ nspk,
                float* __restrict__ out)
{
    // PDL: wait for all primary-grid memory to be visible
    cudaGridDependencySynchronize();

    const int tid  = threadIdx.x;
    const int lane = tid & 31;
    const int b    = tid >> 5;

    __shared__ float sm_s[NB], sm_d[NB], sm_e[NB];

    // ---- transposed partial reduction: lane q sums its statistic ----
    const int q = min(lane, NQ - 1);
    float sq = 0.f;
    {
        const float* base = g_part + (size_t)(b * NBLK) * NQ + q;
#pragma unroll
        for (int blk = 0; blk < NBLK; blk++) sq += base[blk * NQ];
    }
    const int l = min(lane, 8);
    const float dval = g_D[b * 9 + l];
    const float pex  = exist[b * 4 + (lane & 3)];
    const int ns_raw = nspk[b];
    const int ns = min(max(ns_raw, 1), 3);

    // ---- lane l computes S[i][j], D[i][j] for l = 3*i + j ----
    const int i3 = l / 3, j3 = l % 3;
    const float fT = (float)NT;
    float sx  = __shfl_sync(FULLM, sq, i3);
    float sy  = __shfl_sync(FULLM, sq, 3 + j3);
    float sxy = __shfl_sync(FULLM, sq, 6 + l);
    float sxx = __shfl_sync(FULLM, sq, 15 + i3);
    float syy = __shfl_sync(FULLM, sq, 18 + j3);

    float mx = sx / fT, my = sy / fT;
    float estsq = sxx - fT * mx * mx;
    float tgtsq = syy - fT * my * my;
    float dotc  = sxy - fT * mx * my;
    float al  = __fdividef(dotc, tgtsq + EPSF);
    float a2t = al * al * tgtsq;
    float sig = a2t + EPSF;
    float noi = estsq - 2.f * al * dotc + a2t + EPSF;
    float S_l = 10.f * __log10f(__fdividef(sig, noi));
    float D_l = -dval * (1.f / (float)TSUB);

    // ---- lane p evaluates permutation p (bit-packed table) ----
    // perms: {012,021,102,120,201,210}, 2 bits per entry, 6 bits per perm
    const unsigned long long PP =
        0x24ULL | (0x18ULL << 6) | (0x21ULL << 12) |
        (0x09ULL << 18) | (0x12ULL << 24) | (0x06ULL << 30);
    const int p = min(lane, 5);
    bool valid = true;
    float ss = 0.f, dd = 0.f;
#pragma unroll
    for (int slot = 0; slot < 3; slot++) {
        int pi = (int)((PP >> (p * 6 + slot * 2)) & 3ULL);
        int srci = pi * 3 + slot;
        float Sv = __shfl_sync(FULLM, S_l, srci);
        float Dv = __shfl_sync(FULLM, D_l, srci);
        if (!(pi < ns || slot >= ns)) valid = false;
        if (slot < ns) { ss += Sv; dd += Dv; }
    }
    const float inv_n = 1.f / (float)ns;
    float cand_s = valid ? -ss * inv_n : 3.4e38f;
    float cand_d = valid ?  dd * inv_n : 3.4e38f;
    // lanes >=6 hold duplicates of perm 5 -> min unaffected

    // ---- exist BCE: lanes 0..3 ----
    float ev = 0.f;
    if (lane < 4) {
        const int nex = min(ns_raw, 3);
        float t = (lane < nex) ? 1.f : 0.f;
        ev = -(t * fmaxf(__logf(pex), -100.f) +
               (1.f - t) * fmaxf(__logf(1.f - pex), -100.f));
    }

    // ---- full-warp reductions ----
#pragma unroll
    for (int o = 16; o > 0; o >>= 1) {
        cand_s = fminf(cand_s, __shfl_xor_sync(FULLM, cand_s, o));
        cand_d = fminf(cand_d, __shfl_xor_sync(FULLM, cand_d, o));
        ev    += __shfl_xor_sync(FULLM, ev, o);
    }

    if (lane == 0) { sm_s[b] = cand_s; sm_d[b] = cand_d; sm_e[b] = ev; }
    __syncthreads();

    if (b == 0) {
        float rs = warp_sum(sm_s[lane]);
        float rd = warp_sum(sm_d[lane]);
        float re = warp_sum(sm_e[lane]);
        if (lane == 0) {
            float loss_sisnr = rs * (1.f / (float)NB);
            float loss_diar  = rd * (1.f / (float)NB);
            float loss_exist = re * (1.f / (float)(NB * 4));
            float total = loss_sisnr + 0.2f * loss_diar + 0.2f * loss_exist;
            out[0] = total;
            out[1] = loss_sisnr;
            out[2] = loss_diar;
            out[3] = loss_exist;
            out[4] = -loss_sisnr;   // mean_sisnr == -loss_sisnr exactly
        }
    }
}

extern "C" void kernel_launch(void* const* d_in, const int* in_sizes, int n_in,
                              void* d_out, int out_size)
{
    const float* sep = nullptr;
    const float* src = nullptr;
    const float* diar = nullptr;
    const float* lab = nullptr;
    const float* ex = nullptr;
    const int*   ns = nullptr;

    for (int i = 0; i < n_in; i++) {
        switch (in_sizes[i]) {
            case NB * NC * NT:       // 12,288,000: separated first, sources second
                if (!sep) sep = (const float*)d_in[i];
                else       src = (const float*)d_in[i];
                break;
            case NB * TSUB * NC:     // 96,000
                diar = (const float*)d_in[i]; break;
            case NB * (NC + 1):      // 128
                ex = (const float*)d_in[i]; break;
            case NB * TF * NC:       // 768,000
                lab = (const float*)d_in[i]; break;
            case NB:                 // 32
                ns = (const int*)d_in[i]; break;
            default: break;
        }
    }

    main_kernel<<<NB * NBLK + NB, TPB>>>(sep, src, diar, lab);

    // Launch finalize with PDL so its launch/prologue overlaps main_kernel.
    cudaLaunchConfig_t cfg = {};
    cfg.gridDim  = dim3(1, 1, 1);
    cfg.blockDim = dim3(NB * 32, 1, 1);
    cfg.dynamicSmemBytes = 0;
    cfg.stream = 0;
    cudaLaunchAttribute attrs[1];
    attrs[0].id = cudaLaunchAttributeProgrammaticStreamSerialization;
    attrs[0].val.programmaticStreamSerializationAllowed = 1;
    cfg.attrs = attrs;
    cfg.numAttrs = 1;
    cudaLaunchKernelEx(&cfg, finalize_kernel, ex, ns, (float*)d_out);
}

// round 8
// speedup vs baseline: 1.2243x; 1.0171x over previous
#include <cuda_runtime.h>

#define NB    32
#define NC    3
#define NT    128000
#define NT4   (NT/4)        // 32000 float4 per (b,c)
#define TSUB  1000
#define TF    8000
#define NBLK  16            // blocks per batch for the moment pass
#define TPB   256
#define NQ    21            // 3 sum_x + 3 sum_y + 9 sum_xy + 3 sum_xx + 3 sum_yy
#define EPSF  1e-8f
#define FULLM 0xffffffffu
#define GRID  (NB * NBLK + NB)   // 544 blocks

__device__ float g_part[NB * NBLK * NQ];
__device__ float g_D[NB * 9];
__device__ int   g_count;        // zero at load; finalize resets each launch

__device__ __forceinline__ float warp_sum(float v) {
#pragma unroll
    for (int o = 16; o > 0; o >>= 1) v += __shfl_down_sync(FULLM, v, o);
    return v;
}

__global__ void __launch_bounds__(TPB)
main_kernel(const float* __restrict__ sep, const float* __restrict__ src,
            const float* __restrict__ diar, const float* __restrict__ labels)
{
    // Early trigger: let the dependent finalize grid launch NOW so its
    // launch/prologue/spin overlaps this kernel's memory-bound mainloop.
    cudaTriggerProgrammaticLaunchCompletion();

    const int blk  = blockIdx.x;
    const int tid  = threadIdx.x;
    const int lane = tid & 31;
    const int warp = tid >> 5;
    __shared__ float sm[TPB / 32][NQ];

    if (blk < NB * NBLK) {
        // ---- streaming moment accumulation over T ----
        const int b  = blk / NBLK;
        const int bb = blk % NBLK;
        const float4* x0 = (const float4*)(sep + (size_t)(b * 3 + 0) * NT);
        const float4* x1 = (const float4*)(sep + (size_t)(b * 3 + 1) * NT);
        const float4* x2 = (const float4*)(sep + (size_t)(b * 3 + 2) * NT);
        const float4* y0 = (const float4*)(src + (size_t)(b * 3 + 0) * NT);
        const float4* y1 = (const float4*)(src + (size_t)(b * 3 + 1) * NT);
        const float4* y2 = (const float4*)(src + (size_t)(b * 3 + 2) * NT);
        const int chunk = NT4 / NBLK;      // 2000
        const int lo = bb * chunk;
        const int hi = lo + chunk;

        float acc[NQ];
#pragma unroll
        for (int q = 0; q < NQ; q++) acc[q] = 0.f;

        for (int i = lo + tid; i < hi; i += TPB) {
            float4 a0 = x0[i], a1 = x1[i], a2 = x2[i];
            float4 c0 = y0[i], c1 = y1[i], c2 = y2[i];
            const float* pa0 = (const float*)&a0;
            const float* pa1 = (const float*)&a1;
            const float* pa2 = (const float*)&a2;
            const float* pc0 = (const float*)&c0;
            const float* pc1 = (const float*)&c1;
            const float* pc2 = (const float*)&c2;
#pragma unroll
            for (int k = 0; k < 4; k++) {
                float xa = pa0[k], xb = pa1[k], xc = pa2[k];
                float ya = pc0[k], yb = pc1[k], yc = pc2[k];
                acc[0]  += xa;      acc[1]  += xb;      acc[2]  += xc;
                acc[3]  += ya;      acc[4]  += yb;      acc[5]  += yc;
                acc[6]  += xa * ya; acc[7]  += xa * yb; acc[8]  += xa * yc;
                acc[9]  += xb * ya; acc[10] += xb * yb; acc[11] += xb * yc;
                acc[12] += xc * ya; acc[13] += xc * yb; acc[14] += xc * yc;
                acc[15] += xa * xa; acc[16] += xb * xb; acc[17] += xc * xc;
                acc[18] += ya * ya; acc[19] += yb * yb; acc[20] += yc * yc;
            }
        }
#pragma unroll
        for (int q = 0; q < NQ; q++) {
            float v = warp_sum(acc[q]);
            if (lane == 0) sm[warp][q] = v;
        }
        __syncthreads();
        if (warp == 0 && lane < NQ) {
            float s = 0.f;
#pragma unroll
            for (int w = 0; w < TPB / 32; w++) s += sm[w][lane];
            g_part[blk * NQ + lane] = s;
        }
    } else {
        // ---- diarization BCE matrix for one batch ----
        const int b = blk - NB * NBLK;
        const float* dp = diar   + (size_t)b * TSUB * 3;
        const float* lb = labels + (size_t)b * TF * 3;
        float acc[9];
#pragma unroll
        for (int q = 0; q < 9; q++) acc[q] = 0.f;

        for (int t = tid; t < TSUB; t += TPB) {
            float p0 = dp[t * 3 + 0], p1 = dp[t * 3 + 1], p2 = dp[t * 3 + 2];
            // idx = floor(t * (8000/1000)) = 8t
            float l0 = lb[t * 24 + 0], l1 = lb[t * 24 + 1], l2 = lb[t * 24 + 2];
            float lp0 = fmaxf(__logf(p0), -100.f);
            float lp1 = fmaxf(__logf(p1), -100.f);
            float lp2 = fmaxf(__logf(p2), -100.f);
            float lq0 = fmaxf(__logf(1.f - p0), -100.f);
            float lq1 = fmaxf(__logf(1.f - p1), -100.f);
            float lq2 = fmaxf(__logf(1.f - p2), -100.f);
            float m0 = 1.f - l0, m1 = 1.f - l1, m2 = 1.f - l2;
            acc[0] += lp0 * l0 + lq0 * m0;
            acc[1] += lp0 * l1 + lq0 * m1;
            acc[2] += lp0 * l2 + lq0 * m2;
            acc[3] += lp1 * l0 + lq1 * m0;
            acc[4] += lp1 * l1 + lq1 * m1;
            acc[5] += lp1 * l2 + lq1 * m2;
            acc[6] += lp2 * l0 + lq2 * m0;
            acc[7] += lp2 * l1 + lq2 * m1;
            acc[8] += lp2 * l2 + lq2 * m2;
        }
#pragma unroll
        for (int q = 0; q < 9; q++) {
            float v = warp_sum(acc[q]);
            if (lane == 0) sm[warp][q] = v;
        }
        __syncthreads();
        if (warp == 0 && lane < 9) {
            float s = 0.f;
#pragma unroll
            for (int w = 0; w < TPB / 32; w++) s += sm[w][lane];
            g_D[b * 9 + lane] = s;
        }
    }

    // publish: release-fence then bump completion counter
    __syncthreads();
    if (tid == 0) {
        __threadfence();
        atomicAdd(&g_count, 1);
    }
}

// Lane-parallel finalize: warp b handles batch b. Spins (overlapped with the
// primary via early-trigger PDL) until all 544 primary blocks published.
__global__ void __launch_bounds__(NB * 32)
finalize_kernel(const float* __restrict__ exist, const int* __restrict__ nspk,
                float* __restrict__ out)
{
    const int tid  = threadIdx.x;
    const int lane = tid & 31;
    const int b    = tid >> 5;

    __shared__ float sm_s[NB], sm_d[NB], sm_e[NB];

    // ---- spin gate: wait for all primary blocks (acquire) ----
    if (tid == 0) {
        int c;
        do {
            asm volatile("ld.acquire.gpu.s32 %0, [%1];"
                         : "=r"(c) : "l"(&g_count) : "memory");
        } while (c < GRID);
    }
    __syncthreads();
    __threadfence();   // order subsequent reads after the acquire

    // ---- transposed partial reduction: lane q sums its statistic ----
    const int q = min(lane, NQ - 1);
    float sq = 0.f;
    {
        const float* base = g_part + (size_t)(b * NBLK) * NQ + q;
#pragma unroll
        for (int blk = 0; blk < NBLK; blk++) sq += base[blk * NQ];
    }
    const int l = min(lane, 8);
    const float dval = g_D[b * 9 + l];
    const float pex  = exist[b * 4 + (lane & 3)];
    const int ns_raw = nspk[b];
    const int ns = min(max(ns_raw, 1), 3);

    // ---- lane l computes S[i][j], D[i][j] for l = 3*i + j ----
    const int i3 = l / 3, j3 = l % 3;
    const float fT = (float)NT;
    float sx  = __shfl_sync(FULLM, sq, i3);
    float sy  = __shfl_sync(FULLM, sq, 3 + j3);
    float sxy = __shfl_sync(FULLM, sq, 6 + l);
    float sxx = __shfl_sync(FULLM, sq, 15 + i3);
    float syy = __shfl_sync(FULLM, sq, 18 + j3);

    float mx = sx / fT, my = sy / fT;
    float estsq = sxx - fT * mx * mx;
    float tgtsq = syy - fT * my * my;
    float dotc  = sxy - fT * mx * my;
    float al  = __fdividef(dotc, tgtsq + EPSF);
    float a2t = al * al * tgtsq;
    float sig = a2t + EPSF;
    float noi = estsq - 2.f * al * dotc + a2t + EPSF;
    float S_l = 10.f * __log10f(__fdividef(sig, noi));
    float D_l = -dval * (1.f / (float)TSUB);

    // ---- lane p evaluates permutation p (bit-packed table) ----
    // perms: {012,021,102,120,201,210}, 2 bits per entry, 6 bits per perm
    const unsigned long long PP =
        0x24ULL | (0x18ULL << 6) | (0x21ULL << 12) |
        (0x09ULL << 18) | (0x12ULL << 24) | (0x06ULL << 30);
    const int p = min(lane, 5);
    bool valid = true;
    float ss = 0.f, dd = 0.f;
#pragma unroll
    for (int slot = 0; slot < 3; slot++) {
        int pi = (int)((PP >> (p * 6 + slot * 2)) & 3ULL);
        int srci = pi * 3 + slot;
        float Sv = __shfl_sync(FULLM, S_l, srci);
        float Dv = __shfl_sync(FULLM, D_l, srci);
        if (!(pi < ns || slot >= ns)) valid = false;
        if (slot < ns) { ss += Sv; dd += Dv; }
    }
    const float inv_n = 1.f / (float)ns;
    float cand_s = valid ? -ss * inv_n : 3.4e38f;
    float cand_d = valid ?  dd * inv_n : 3.4e38f;
    // lanes >=6 hold duplicates of perm 5 -> min unaffected

    // ---- exist BCE: lanes 0..3 ----
    float ev = 0.f;
    if (lane < 4) {
        const int nex = min(ns_raw, 3);
        float t = (lane < nex) ? 1.f : 0.f;
        ev = -(t * fmaxf(__logf(pex), -100.f) +
               (1.f - t) * fmaxf(__logf(1.f - pex), -100.f));
    }

    // ---- full-warp reductions ----
#pragma unroll
    for (int o = 16; o > 0; o >>= 1) {
        cand_s = fminf(cand_s, __shfl_xor_sync(FULLM, cand_s, o));
        cand_d = fminf(cand_d, __shfl_xor_sync(FULLM, cand_d, o));
        ev    += __shfl_xor_sync(FULLM, ev, o);
    }

    if (lane == 0) { sm_s[b] = cand_s; sm_d[b] = cand_d; sm_e[b] = ev; }
    __syncthreads();

    if (b == 0) {
        float rs = warp_sum(sm_s[lane]);
        float rd = warp_sum(sm_d[lane]);
        float re = warp_sum(sm_e[lane]);
        if (lane == 0) {
            float loss_sisnr = rs * (1.f / (float)NB);
            float loss_diar  = rd * (1.f / (float)NB);
            float loss_exist = re * (1.f / (float)(NB * 4));
            float total = loss_sisnr + 0.2f * loss_diar + 0.2f * loss_exist;
            out[0] = total;
            out[1] = loss_sisnr;
            out[2] = loss_diar;
            out[3] = loss_exist;
            out[4] = -loss_sisnr;   // mean_sisnr == -loss_sisnr exactly
            g_count = 0;            // reset for the next (deterministic) replay
        }
    }
}

extern "C" void kernel_launch(void* const* d_in, const int* in_sizes, int n_in,
                              void* d_out, int out_size)
{
    const float* sep = nullptr;
    const float* src = nullptr;
    const float* diar = nullptr;
    const float* lab = nullptr;
    const float* ex = nullptr;
    const int*   ns = nullptr;

    for (int i = 0; i < n_in; i++) {
        switch (in_sizes[i]) {
            case NB * NC * NT:       // 12,288,000: separated first, sources second
                if (!sep) sep = (const float*)d_in[i];
                else       src = (const float*)d_in[i];
                break;
            case NB * TSUB * NC:     // 96,000
                diar = (const float*)d_in[i]; break;
            case NB * (NC + 1):      // 128
                ex = (const float*)d_in[i]; break;
            case NB * TF * NC:       // 768,000
                lab = (const float*)d_in[i]; break;
            case NB:                 // 32
                ns = (const int*)d_in[i]; break;
            default: break;
        }
    }

    main_kernel<<<GRID, TPB>>>(sep, src, diar, lab);

    // PDL: finalize launches as soon as primary blocks hit the early trigger;
    // its own spin gate provides the data dependency.
    cudaLaunchConfig_t cfg = {};
    cfg.gridDim  = dim3(1, 1, 1);
    cfg.blockDim = dim3(NB * 32, 1, 1);
    cfg.dynamicSmemBytes = 0;
    cfg.stream = 0;
    cudaLaunchAttribute attrs[1];
    attrs[0].id = cudaLaunchAttributeProgrammaticStreamSerialization;
    attrs[0].val.programmaticStreamSerializationAllowed = 1;
    cfg.attrs = attrs;
    cfg.numAttrs = 1;
    cudaLaunchKernelEx(&cfg, finalize_kernel, ex, ns, (float*)d_out);
}